// round 1
// baseline (speedup 1.0000x reference)
#include <cuda_runtime.h>
#include <math.h>

#define NUM_HEADS_C 16
#define SEQ_C 1024
#define HD_C 64
#define NH_C 64
#define SCALE_C 0.125f

// 256 MB scratch for the full positional score matrix P[n, i, t] = Qv[n,i] . R[h,t]
__device__ float g_pos[(size_t)NH_C * SEQ_C * SEQ_C];

// ---------------------------------------------------------------------------
// Kernel 1: P[n, i, t] = (q[n,i,:]*scale + v_bias[h,:]) . R[h, t, :]
// Tiled GEMM, BM=BN=64, K=64 (single panel), 256 threads, 4x4 micro-tile.
// ---------------------------------------------------------------------------
__global__ __launch_bounds__(256, 2)
void pos_gemm_kernel(const float* __restrict__ q,
                     const float* __restrict__ vbias,
                     const float* __restrict__ R)
{
    __shared__ float Qs[64 * 68];   // [d][i] transposed, pad 68 for f4 + conflict-free stores
    __shared__ float Rs[64 * 68];   // [d][t] transposed

    const int tid = threadIdx.x;
    const int n  = blockIdx.z;
    const int h  = n & 15;
    const int i0 = blockIdx.y << 6;
    const int t0 = blockIdx.x << 6;

    const float* qb = q + (size_t)n * (SEQ_C * HD_C) + (size_t)i0 * HD_C;
    const float* rb = R + (size_t)h * (2048 * HD_C) + (size_t)t0 * HD_C;

    #pragma unroll
    for (int it = 0; it < 16; ++it) {
        int idx = it * 256 + tid;
        int r = idx >> 6, c = idx & 63;
        Qs[c * 68 + r] = qb[idx] * SCALE_C + vbias[h * 64 + c];
        Rs[c * 68 + r] = rb[idx];
    }
    __syncthreads();

    const int ty = tid >> 4, tx = tid & 15;
    float acc[4][4] = {};

    #pragma unroll 8
    for (int kd = 0; kd < 64; ++kd) {
        float4 a = *(const float4*)(Qs + kd * 68 + ty * 4);
        float4 b = *(const float4*)(Rs + kd * 68 + tx * 4);
        acc[0][0] += a.x * b.x; acc[0][1] += a.x * b.y; acc[0][2] += a.x * b.z; acc[0][3] += a.x * b.w;
        acc[1][0] += a.y * b.x; acc[1][1] += a.y * b.y; acc[1][2] += a.y * b.z; acc[1][3] += a.y * b.w;
        acc[2][0] += a.z * b.x; acc[2][1] += a.z * b.y; acc[2][2] += a.z * b.z; acc[2][3] += a.z * b.w;
        acc[3][0] += a.w * b.x; acc[3][1] += a.w * b.y; acc[3][2] += a.w * b.z; acc[3][3] += a.w * b.w;
    }

    float* ob = g_pos + ((size_t)n << 20) + ((size_t)(i0 + ty * 4) << 10) + t0 + tx * 4;
    #pragma unroll
    for (int ii = 0; ii < 4; ++ii)
        *(float4*)(ob + ((size_t)ii << 10)) =
            make_float4(acc[ii][0], acc[ii][1], acc[ii][2], acc[ii][3]);
}

// ---------------------------------------------------------------------------
// Kernel 2: flash attention with shifted positional scores gathered from g_pos.
//   score[i,j] = (q[i]*scale + u_bias) . K[j] + shift(P)[i,j]
//   shift(P)[i,j] = P[i, 1023+j-i]   (j <= i)
//                 = 0                (j == i+1)
//                 = P[i+1, j-i-2]    (j >= i+2)
// BM=BN=64, online softmax, 256 threads, 4x4 micro-tiles.
// ---------------------------------------------------------------------------
__global__ __launch_bounds__(256, 2)
void flash_kernel(const float* __restrict__ q,
                  const float* __restrict__ k,
                  const float* __restrict__ v,
                  const float* __restrict__ ubias,
                  float* __restrict__ out)
{
    extern __shared__ float sm[];
    float* Qus = sm;                 // [64][68] d-major (transposed)
    float* Ks  = sm + 64 * 68;       // [64][68] d-major (transposed)
    float* Ps  = sm + 2 * 64 * 68;   // [64][68] i-major probs
    float* Vs  = sm + 3 * 64 * 68;   // [64][64] j-major (natural)

    const int tid = threadIdx.x;
    const int ty = tid >> 4, tx = tid & 15;
    const int n  = blockIdx.y;
    const int h  = n & 15;
    const int i0 = blockIdx.x << 6;

    const float* qb = q + (size_t)n * 65536 + (size_t)i0 * 64;
    #pragma unroll
    for (int it = 0; it < 16; ++it) {
        int idx = it * 256 + tid;
        int r = idx >> 6, c = idx & 63;
        Qus[c * 68 + r] = qb[idx] * SCALE_C + ubias[h * 64 + c];
    }

    float m[4], l[4], O[4][4];
    #pragma unroll
    for (int ii = 0; ii < 4; ++ii) {
        m[ii] = -1e30f; l[ii] = 0.0f;
        #pragma unroll
        for (int jj = 0; jj < 4; ++jj) O[ii][jj] = 0.0f;
    }

    const float* posb = g_pos + ((size_t)n << 20);
    const float* kb0  = k + (size_t)n * 65536;
    const float* vb0  = v + (size_t)n * 65536;

    for (int kt = 0; kt < 16; ++kt) {
        const int j0 = kt << 6;
        __syncthreads();   // previous PV done reading Ps/Vs; Qus safe (written pre-loop)

        const float* kb = kb0 + (size_t)j0 * 64;
        const float* vb = vb0 + (size_t)j0 * 64;
        #pragma unroll
        for (int it = 0; it < 16; ++it) {
            int idx = it * 256 + tid;
            int r = idx >> 6, c = idx & 63;
            Ks[c * 68 + r] = kb[idx];
            Vs[idx] = vb[idx];
        }
        __syncthreads();

        // content scores
        float acc[4][4] = {};
        #pragma unroll 8
        for (int kd = 0; kd < 64; ++kd) {
            float4 a = *(const float4*)(Qus + kd * 68 + ty * 4);
            float4 b = *(const float4*)(Ks  + kd * 68 + tx * 4);
            acc[0][0] += a.x * b.x; acc[0][1] += a.x * b.y; acc[0][2] += a.x * b.z; acc[0][3] += a.x * b.w;
            acc[1][0] += a.y * b.x; acc[1][1] += a.y * b.y; acc[1][2] += a.y * b.z; acc[1][3] += a.y * b.w;
            acc[2][0] += a.z * b.x; acc[2][1] += a.z * b.y; acc[2][2] += a.z * b.z; acc[2][3] += a.z * b.w;
            acc[3][0] += a.w * b.x; acc[3][1] += a.w * b.y; acc[3][2] += a.w * b.z; acc[3][3] += a.w * b.w;
        }

        // add shifted positional scores (gather from g_pos)
        #pragma unroll
        for (int ii = 0; ii < 4; ++ii) {
            const int i = i0 + ty * 4 + ii;
            #pragma unroll
            for (int jj = 0; jj < 4; ++jj) {
                const int j = j0 + tx * 4 + jj;
                float p;
                if (j <= i)          p = posb[((size_t)i << 10) + (size_t)(1023 - i + j)];
                else if (j == i + 1) p = 0.0f;
                else                 p = posb[((size_t)(i + 1) << 10) + (size_t)(j - i - 2)];
                acc[ii][jj] += p;
            }
        }

        // online softmax update (row groups share ty -> 16-lane shuffle reductions)
        #pragma unroll
        for (int ii = 0; ii < 4; ++ii) {
            float tm = fmaxf(fmaxf(acc[ii][0], acc[ii][1]), fmaxf(acc[ii][2], acc[ii][3]));
            #pragma unroll
            for (int off = 1; off < 16; off <<= 1)
                tm = fmaxf(tm, __shfl_xor_sync(0xffffffffu, tm, off));
            float mn = fmaxf(m[ii], tm);
            float corr = __expf(m[ii] - mn);
            m[ii] = mn;
            float rs = 0.0f;
            #pragma unroll
            for (int jj = 0; jj < 4; ++jj) {
                acc[ii][jj] = __expf(acc[ii][jj] - mn);
                rs += acc[ii][jj];
            }
            #pragma unroll
            for (int off = 1; off < 16; off <<= 1)
                rs += __shfl_xor_sync(0xffffffffu, rs, off);
            l[ii] = l[ii] * corr + rs;
            #pragma unroll
            for (int jj = 0; jj < 4; ++jj) O[ii][jj] *= corr;
        }

        // store probs (float4, conflict-free)
        #pragma unroll
        for (int ii = 0; ii < 4; ++ii)
            *(float4*)(Ps + (ty * 4 + ii) * 68 + tx * 4) =
                make_float4(acc[ii][0], acc[ii][1], acc[ii][2], acc[ii][3]);
        __syncthreads();

        // O += probs @ V
        #pragma unroll 4
        for (int j = 0; j < 64; j += 4) {
            float4 b0 = *(const float4*)(Vs + (j + 0) * 64 + tx * 4);
            float4 b1 = *(const float4*)(Vs + (j + 1) * 64 + tx * 4);
            float4 b2 = *(const float4*)(Vs + (j + 2) * 64 + tx * 4);
            float4 b3 = *(const float4*)(Vs + (j + 3) * 64 + tx * 4);
            #pragma unroll
            for (int ii = 0; ii < 4; ++ii) {
                float4 a = *(const float4*)(Ps + (ty * 4 + ii) * 68 + j);
                O[ii][0] += a.x * b0.x + a.y * b1.x + a.z * b2.x + a.w * b3.x;
                O[ii][1] += a.x * b0.y + a.y * b1.y + a.z * b2.y + a.w * b3.y;
                O[ii][2] += a.x * b0.z + a.y * b1.z + a.z * b2.z + a.w * b3.z;
                O[ii][3] += a.x * b0.w + a.y * b1.w + a.z * b2.w + a.w * b3.w;
            }
        }
    }

    float* ob = out + (size_t)n * 65536 + (size_t)(i0 + ty * 4) * 64 + tx * 4;
    #pragma unroll
    for (int ii = 0; ii < 4; ++ii) {
        float inv = 1.0f / l[ii];
        *(float4*)(ob + ii * 64) =
            make_float4(O[ii][0] * inv, O[ii][1] * inv, O[ii][2] * inv, O[ii][3] * inv);
    }
}

// ---------------------------------------------------------------------------
extern "C" void kernel_launch(void* const* d_in, const int* in_sizes, int n_in,
                              void* d_out, int out_size)
{
    const float* q  = (const float*)d_in[0];
    const float* k  = (const float*)d_in[1];
    const float* v  = (const float*)d_in[2];
    const float* ub = (const float*)d_in[3];
    const float* vb = (const float*)d_in[4];
    const float* R  = (const float*)d_in[5];
    float* out = (float*)d_out;

    const int SMEM2 = (3 * 64 * 68 + 64 * 64) * (int)sizeof(float);  // 68608 B
    cudaFuncSetAttribute(flash_kernel, cudaFuncAttributeMaxDynamicSharedMemorySize, SMEM2);

    pos_gemm_kernel<<<dim3(16, 16, 64), 256>>>(q, vb, R);
    flash_kernel<<<dim3(16, 64), 256, SMEM2>>>(q, k, v, ub, out);
}